// round 14
// baseline (speedup 1.0000x reference)
#include <cuda_runtime.h>
#include <cuda_fp16.h>
#include <cstdint>

// ---------------------------------------------------------------------------
// GCN forward:  N=50000, E=800000, F_IN=128, H=256, G=256, O=32, L=3
// edge_index / batch are int32.
//
// fp16 end-to-end; mma.sync m16n8k16.  Middle layers run as FUSED kernels:
// one CTA aggregates 128 dst nodes into smem (h tile) then immediately does
// the next layer's GEMM on that tile (A never leaves smem). hw ping-pongs.
// Chain: ENC -> G1 -> [A1+G2] -> [A2+G3] -> A3 -> pool/readout.
// ---------------------------------------------------------------------------

#define NN 50000
#define NE 800000
#define FIN 128
#define HD 256
#define NG 256
#define NO 32
#define NL 3
#define ETOT (NE + NN)
#define SCB 49

// ----------------------------- device scratch ------------------------------
__device__ __half   g_hf16[(size_t)NN * HD];         // fp16 h (ENC out / last agg out)
__device__ __half   g_xh[(size_t)NN * FIN];          // fp16 x
__device__ __half   g_hw0[(size_t)NN * HD];          // fp16 hw ping
__device__ __half   g_hw1[(size_t)NN * HD];          // fp16 hw pong
__device__ int      g_counts[NN];
__device__ int      g_cursor[NN];
__device__ float    g_dis[NN];
__device__ int      g_offsets[NN + 1];
__device__ int      g_part[SCB];
__device__ int2     g_csr[ETOT];
__device__ int      g_gstart[NG + 1];
__device__ uint32_t g_wp_enc[(FIN / 2) * HD];
__device__ uint32_t g_wp_conv[NL * (HD / 2) * HD];

// ------------------------------ setup kernels ------------------------------
__global__ void k_init() {
    int i = blockIdx.x * blockDim.x + threadIdx.x;
    if (i < NN) g_counts[i] = 1;                     // self loop
}

__global__ void k_count_deg(const int* __restrict__ ei) {
    int e = blockIdx.x * blockDim.x + threadIdx.x;
    if (e < NE) atomicAdd(&g_counts[ei[NE + e]], 1);
}

__global__ void __launch_bounds__(1024) k_scan_local() {
    __shared__ int sd[1024];
    int t = threadIdx.x;
    int i = blockIdx.x * 1024 + t;
    int v = 0;
    if (i < NN) {
        v = g_counts[i];
        g_dis[i] = rsqrtf((float)v);
    }
    sd[t] = v;
    __syncthreads();
    #pragma unroll
    for (int off = 1; off < 1024; off <<= 1) {
        int tmp = (t >= off) ? sd[t - off] : 0;
        __syncthreads();
        if (t >= off) sd[t] += tmp;
        __syncthreads();
    }
    if (i < NN) g_offsets[i + 1] = sd[t];
    if (t == 1023) g_part[blockIdx.x] = sd[t];
}

__global__ void __launch_bounds__(1024) k_scan_add() {
    __shared__ int sp[64];
    int t = threadIdx.x;
    if (t < 64) sp[t] = (t < SCB) ? g_part[t] : 0;
    __syncthreads();
    #pragma unroll
    for (int off = 1; off < 64; off <<= 1) {
        int v = (t < 64 && t >= off) ? sp[t - off] : 0;
        __syncthreads();
        if (t < 64) sp[t] += v;
        __syncthreads();
    }
    int prefix = (blockIdx.x == 0) ? 0 : sp[blockIdx.x - 1];
    int i = blockIdx.x * 1024 + t;
    if (i < NN) {
        g_offsets[i + 1] += prefix;
        g_cursor[i] = 0;
    }
    if (i == 0) g_offsets[0] = 0;
}

__global__ void k_fill(const int* __restrict__ ei) {
    int idx = blockIdx.x * blockDim.x + threadIdx.x;
    if (idx < NN) {
        int pos = g_offsets[idx] + atomicAdd(&g_cursor[idx], 1);
        float d = g_dis[idx];
        g_csr[pos] = make_int2(idx, __float_as_int(d * d));
    } else if (idx < NN + NE) {
        int e = idx - NN;
        int s = ei[e];
        int d = ei[NE + e];
        int pos = g_offsets[d] + atomicAdd(&g_cursor[d], 1);
        g_csr[pos] = make_int2(s, __float_as_int(g_dis[s] * g_dis[d]));
    }
}

// --------- input convert + weight pack + graph bounds (merged, once) --------
__global__ void __launch_bounds__(256) k_prep(const float* __restrict__ x,
                                              const float* __restrict__ enc_w,
                                              const float* __restrict__ conv_w,
                                              const int* __restrict__ batch) {
    int i = blockIdx.x * blockDim.x + threadIdx.x;
    const int XT  = NN * FIN / 2;
    const int NE_ = (FIN / 2) * HD;
    const int NC_ = NL * (HD / 2) * HD;
    if (i < XT) {
        float2 f = ((const float2*)x)[i];
        ((__half2*)g_xh)[i] = __floats2half2_rn(f.x, f.y);
        return;
    }
    int j = i - XT;
    if (j < NE_) {
        int p = j / HD, n = j % HD;
        __half2 h = __floats2half2_rn(enc_w[(2 * p) * HD + n],
                                      enc_w[(2 * p + 1) * HD + n]);
        g_wp_enc[j] = *reinterpret_cast<uint32_t*>(&h);
        return;
    }
    int r0 = j - NE_;
    if (r0 < NC_) {
        int l = r0 / ((HD / 2) * HD);
        int r = r0 % ((HD / 2) * HD);
        int p = r / HD, n = r % HD;
        const float* W = conv_w + (size_t)l * HD * HD;
        __half2 h = __floats2half2_rn(W[(2 * p) * HD + n],
                                      W[(2 * p + 1) * HD + n]);
        g_wp_conv[r0] = *reinterpret_cast<uint32_t*>(&h);
        return;
    }
    int g = r0 - NC_;
    if (g <= NG) {
        int lo = 0, hi = NN;
        while (lo < hi) {
            int mid = (lo + hi) >> 1;
            if (batch[mid] < g) lo = mid + 1; else hi = mid;
        }
        g_gstart[g] = lo;
    }
}

// ----------------------- fp16 tensor-core GEMM (R11) -------------------------
__device__ __forceinline__ void mma_f16(float* c, const uint32_t* a,
                                        uint32_t b0, uint32_t b1) {
    asm volatile(
        "mma.sync.aligned.m16n8k16.row.col.f32.f16.f16.f32 "
        "{%0,%1,%2,%3}, {%4,%5,%6,%7}, {%8,%9}, {%0,%1,%2,%3};"
        : "+f"(c[0]), "+f"(c[1]), "+f"(c[2]), "+f"(c[3])
        : "r"(a[0]), "r"(a[1]), "r"(a[2]), "r"(a[3]), "r"(b0), "r"(b1));
}

__global__ void __launch_bounds__(256) k_gemm_f16(
    const __half* __restrict__ A, const uint32_t* __restrict__ Wp,
    const float* __restrict__ bias, __half* __restrict__ Ch,
    int M, int K)
{
    __shared__ uint32_t As[2][8][136];
    __shared__ uint32_t Bs[2][8][136];

    int tid = threadIdx.x;
    int bm = blockIdx.x * 128;
    int bn = blockIdx.y * 128;

    int lane = tid & 31;
    int warp = tid >> 5;
    int tig  = lane & 3;
    int grp  = lane >> 2;
    int wm   = (warp & 3) * 32;
    int wn   = (warp >> 2) * 64;

    int ar  = bm + (tid >> 1);  if (ar >= M) ar = M - 1;
    int akq = (tid & 1) * 8;
    int ap2 = akq >> 1;
    int bk  = tid >> 5;
    int bc  = (tid & 31) * 4;

    const __half*   Apt = A + (size_t)ar * K + akq;
    const uint32_t* Bpt = Wp + (size_t)bk * HD + bn + bc;

    float acc[2][8][4];
    #pragma unroll
    for (int mt = 0; mt < 2; mt++)
        #pragma unroll
        for (int nt = 0; nt < 8; nt++)
            #pragma unroll
            for (int r = 0; r < 4; r++) acc[mt][nt][r] = 0.f;

    int KT = K >> 4;

    uint4 rA = *(const uint4*)(Apt);
    uint4 rB = *(const uint4*)(Bpt);
    {
        int arow = tid >> 1;
        As[0][ap2 + 0][arow] = rA.x;
        As[0][ap2 + 1][arow] = rA.y;
        As[0][ap2 + 2][arow] = rA.z;
        As[0][ap2 + 3][arow] = rA.w;
        Bs[0][bk][bc + 0] = rB.x;
        Bs[0][bk][bc + 1] = rB.y;
        Bs[0][bk][bc + 2] = rB.z;
        Bs[0][bk][bc + 3] = rB.w;
    }
    __syncthreads();

    for (int kt = 0; kt < KT; kt++) {
        int cur = kt & 1;
        int nxt = cur ^ 1;
        if (kt + 1 < KT) {
            rA = *(const uint4*)(Apt + (kt + 1) * 16);
            rB = *(const uint4*)(Bpt + (size_t)(kt + 1) * 8 * HD);
        }
        uint32_t a[2][4];
        #pragma unroll
        for (int mt = 0; mt < 2; mt++) {
            int rb = wm + mt * 16 + grp;
            a[mt][0] = As[cur][tig][rb];
            a[mt][1] = As[cur][tig][rb + 8];
            a[mt][2] = As[cur][tig + 4][rb];
            a[mt][3] = As[cur][tig + 4][rb + 8];
        }
        #pragma unroll
        for (int nt = 0; nt < 8; nt++) {
            int nb = wn + nt * 8 + grp;
            uint32_t b0 = Bs[cur][tig][nb];
            uint32_t b1 = Bs[cur][tig + 4][nb];
            mma_f16(acc[0][nt], a[0], b0, b1);
            mma_f16(acc[1][nt], a[1], b0, b1);
        }
        if (kt + 1 < KT) {
            int arow = tid >> 1;
            As[nxt][ap2 + 0][arow] = rA.x;
            As[nxt][ap2 + 1][arow] = rA.y;
            As[nxt][ap2 + 2][arow] = rA.z;
            As[nxt][ap2 + 3][arow] = rA.w;
            Bs[nxt][bk][bc + 0] = rB.x;
            Bs[nxt][bk][bc + 1] = rB.y;
            Bs[nxt][bk][bc + 2] = rB.z;
            Bs[nxt][bk][bc + 3] = rB.w;
        }
        __syncthreads();
    }

    #pragma unroll
    for (int mt = 0; mt < 2; mt++) {
        #pragma unroll
        for (int nt = 0; nt < 8; nt++) {
            int col = bn + wn + nt * 8 + tig * 2;
            float b0 = bias ? bias[col]     : 0.f;
            float b1 = bias ? bias[col + 1] : 0.f;
            int r0 = bm + wm + mt * 16 + grp;
            int r1 = r0 + 8;
            if (r0 < M) {
                __half2 v = __floats2half2_rn(acc[mt][nt][0] + b0,
                                              acc[mt][nt][1] + b1);
                *(__half2*)(Ch + (size_t)r0 * HD + col) = v;
            }
            if (r1 < M) {
                __half2 v = __floats2half2_rn(acc[mt][nt][2] + b0,
                                              acc[mt][nt][3] + b1);
                *(__half2*)(Ch + (size_t)r1 * HD + col) = v;
            }
        }
    }
}

// ------------------- FUSED aggregate_l + GEMM_{l+1} --------------------------
// One CTA: rows [bm, bm+128). Phase 1: aggregate into smem A tile
// (row-major [128][132] uint32 = half2 kpairs). Phase 2: mma over K=256,
// two 128-col passes; writes hw_out.  smem = 128*132*4 + 2*8*136*4 = 76288 B.
#define A2PITCH 132
#define FUSED_SMEM ((128 * A2PITCH + 2 * 8 * 136) * 4)

__global__ void __launch_bounds__(256) k_agg_gemm(
    const float* __restrict__ bias, const __half* __restrict__ hw_in,
    const uint32_t* __restrict__ Wn, __half* __restrict__ hw_out)
{
    extern __shared__ uint32_t smf[];
    uint32_t* As2 = smf;                                // [128][A2PITCH]
    uint32_t (*Bs)[8][136] =
        reinterpret_cast<uint32_t(*)[8][136]>(smf + 128 * A2PITCH);

    int tid  = threadIdx.x;
    int lane = tid & 31;
    int warp = tid >> 5;
    int bm   = blockIdx.x * 128;

    // ---------------- phase 1: aggregate 128 rows into As2 ----------------
    const uint4* hwv = (const uint4*)hw_in;
    float4 bA = ((const float4*)bias)[lane * 2];
    float4 bB = ((const float4*)bias)[lane * 2 + 1];
    for (int r = warp; r < 128; r += 8) {
        int i = bm + r;
        if (i < NN) {
            int beg = g_offsets[i];
            int end = g_offsets[i + 1];
            float acc[8], acc2[8];
            acc[0] = bA.x; acc[1] = bA.y; acc[2] = bA.z; acc[3] = bA.w;
            acc[4] = bB.x; acc[5] = bB.y; acc[6] = bB.z; acc[7] = bB.w;
            #pragma unroll
            for (int j = 0; j < 8; j++) acc2[j] = 0.f;
            int e = beg;
            for (; e + 2 <= end; e += 2) {
                int2 p0 = __ldg(&g_csr[e]);
                int2 p1 = __ldg(&g_csr[e + 1]);
                float w0 = __int_as_float(p0.y);
                float w1 = __int_as_float(p1.y);
                uint4 v0 = __ldg(&hwv[(size_t)p0.x * 32 + lane]);
                uint4 v1 = __ldg(&hwv[(size_t)p1.x * 32 + lane]);
                const __half2* h0 = (const __half2*)&v0;
                const __half2* h1 = (const __half2*)&v1;
                #pragma unroll
                for (int j = 0; j < 4; j++) {
                    float2 f0 = __half22float2(h0[j]);
                    float2 f1 = __half22float2(h1[j]);
                    acc[2*j]   = fmaf(w0, f0.x, acc[2*j]);
                    acc[2*j+1] = fmaf(w0, f0.y, acc[2*j+1]);
                    acc2[2*j]   = fmaf(w1, f1.x, acc2[2*j]);
                    acc2[2*j+1] = fmaf(w1, f1.y, acc2[2*j+1]);
                }
            }
            if (e < end) {
                int2 p = __ldg(&g_csr[e]);
                float w = __int_as_float(p.y);
                uint4 v = __ldg(&hwv[(size_t)p.x * 32 + lane]);
                const __half2* hh = (const __half2*)&v;
                #pragma unroll
                for (int j = 0; j < 4; j++) {
                    float2 f = __half22float2(hh[j]);
                    acc[2*j]   = fmaf(w, f.x, acc[2*j]);
                    acc[2*j+1] = fmaf(w, f.y, acc[2*j+1]);
                }
            }
            #pragma unroll
            for (int j = 0; j < 8; j++) acc[j] += acc2[j];
            uint4 ho;
            __half2 q0 = __floats2half2_rn(acc[0], acc[1]);
            __half2 q1 = __floats2half2_rn(acc[2], acc[3]);
            __half2 q2 = __floats2half2_rn(acc[4], acc[5]);
            __half2 q3 = __floats2half2_rn(acc[6], acc[7]);
            ho.x = *reinterpret_cast<uint32_t*>(&q0);
            ho.y = *reinterpret_cast<uint32_t*>(&q1);
            ho.z = *reinterpret_cast<uint32_t*>(&q2);
            ho.w = *reinterpret_cast<uint32_t*>(&q3);
            *(uint4*)&As2[r * A2PITCH + lane * 4] = ho;   // kpairs 4t..4t+3
        }
    }
    __syncthreads();

    // ---------------- phase 2: GEMM, two 128-col passes ----------------
    int tig = lane & 3;
    int grp = lane >> 2;
    int wm  = (warp & 3) * 32;
    int wn  = (warp >> 2) * 64;
    int bk  = tid >> 5;
    int bc  = (tid & 31) * 4;

    #pragma unroll
    for (int half = 0; half < 2; half++) {
        int bn = half * 128;
        const uint32_t* Bpt = Wn + (size_t)bk * HD + bn + bc;

        float acc[2][8][4];
        #pragma unroll
        for (int mt = 0; mt < 2; mt++)
            #pragma unroll
            for (int nt = 0; nt < 8; nt++)
                #pragma unroll
                for (int r = 0; r < 4; r++) acc[mt][nt][r] = 0.f;

        uint4 rB = *(const uint4*)(Bpt);
        Bs[0][bk][bc + 0] = rB.x;
        Bs[0][bk][bc + 1] = rB.y;
        Bs[0][bk][bc + 2] = rB.z;
        Bs[0][bk][bc + 3] = rB.w;
        __syncthreads();

        #pragma unroll
        for (int kt = 0; kt < 16; kt++) {
            int cur = kt & 1;
            int nxt = cur ^ 1;
            if (kt + 1 < 16)
                rB = *(const uint4*)(Bpt + (size_t)(kt + 1) * 8 * HD);

            uint32_t a[2][4];
            #pragma unroll
            for (int mt = 0; mt < 2; mt++) {
                int rb = wm + mt * 16 + grp;
                int k8 = kt * 8;
                a[mt][0] = As2[rb * A2PITCH + k8 + tig];
                a[mt][1] = As2[(rb + 8) * A2PITCH + k8 + tig];
                a[mt][2] = As2[rb * A2PITCH + k8 + tig + 4];
                a[mt][3] = As2[(rb + 8) * A2PITCH + k8 + tig + 4];
            }
            #pragma unroll
            for (int nt = 0; nt < 8; nt++) {
                int nb = wn + nt * 8 + grp;
                uint32_t b0 = Bs[cur][tig][nb];
                uint32_t b1 = Bs[cur][tig + 4][nb];
                mma_f16(acc[0][nt], a[0], b0, b1);
                mma_f16(acc[1][nt], a[1], b0, b1);
            }
            if (kt + 1 < 16) {
                Bs[nxt][bk][bc + 0] = rB.x;
                Bs[nxt][bk][bc + 1] = rB.y;
                Bs[nxt][bk][bc + 2] = rB.z;
                Bs[nxt][bk][bc + 3] = rB.w;
            }
            __syncthreads();
        }

        #pragma unroll
        for (int mt = 0; mt < 2; mt++) {
            #pragma unroll
            for (int nt = 0; nt < 8; nt++) {
                int col = bn + wn + nt * 8 + tig * 2;
                int r0 = bm + wm + mt * 16 + grp;
                int r1 = r0 + 8;
                if (r0 < NN) {
                    __half2 v = __floats2half2_rn(acc[mt][nt][0], acc[mt][nt][1]);
                    *(__half2*)(hw_out + (size_t)r0 * HD + col) = v;
                }
                if (r1 < NN) {
                    __half2 v = __floats2half2_rn(acc[mt][nt][2], acc[mt][nt][3]);
                    *(__half2*)(hw_out + (size_t)r1 * HD + col) = v;
                }
            }
        }
        __syncthreads();   // Bs reused by next half
    }
}

// ----------------------------- CSR aggregation (last layer) -----------------
__global__ void __launch_bounds__(256) k_aggregate(
    const float* __restrict__ bias, const __half* __restrict__ hw)
{
    int grpIdx = threadIdx.x >> 5;
    int t      = threadIdx.x & 31;
    int i = blockIdx.x * 8 + grpIdx;
    if (i >= NN) return;
    int beg = g_offsets[i];
    int end = g_offsets[i + 1];

    float acc[8], acc2[8];
    {
        float4 bA = ((const float4*)bias)[t * 2];
        float4 bB = ((const float4*)bias)[t * 2 + 1];
        acc[0] = bA.x; acc[1] = bA.y; acc[2] = bA.z; acc[3] = bA.w;
        acc[4] = bB.x; acc[5] = bB.y; acc[6] = bB.z; acc[7] = bB.w;
        #pragma unroll
        for (int j = 0; j < 8; j++) acc2[j] = 0.f;
    }

    const uint4* hwv = (const uint4*)hw;
    int e = beg;
    for (; e + 2 <= end; e += 2) {
        int2 p0 = __ldg(&g_csr[e]);
        int2 p1 = __ldg(&g_csr[e + 1]);
        float w0 = __int_as_float(p0.y);
        float w1 = __int_as_float(p1.y);
        uint4 v0 = __ldg(&hwv[(size_t)p0.x * 32 + t]);
        uint4 v1 = __ldg(&hwv[(size_t)p1.x * 32 + t]);
        const __half2* h0 = (const __half2*)&v0;
        const __half2* h1 = (const __half2*)&v1;
        #pragma unroll
        for (int j = 0; j < 4; j++) {
            float2 f0 = __half22float2(h0[j]);
            float2 f1 = __half22float2(h1[j]);
            acc[2*j]   = fmaf(w0, f0.x, acc[2*j]);
            acc[2*j+1] = fmaf(w0, f0.y, acc[2*j+1]);
            acc2[2*j]   = fmaf(w1, f1.x, acc2[2*j]);
            acc2[2*j+1] = fmaf(w1, f1.y, acc2[2*j+1]);
        }
    }
    if (e < end) {
        int2 p = __ldg(&g_csr[e]);
        float w = __int_as_float(p.y);
        uint4 v = __ldg(&hwv[(size_t)p.x * 32 + t]);
        const __half2* hh = (const __half2*)&v;
        #pragma unroll
        for (int j = 0; j < 4; j++) {
            float2 f = __half22float2(hh[j]);
            acc[2*j]   = fmaf(w, f.x, acc[2*j]);
            acc[2*j+1] = fmaf(w, f.y, acc[2*j+1]);
        }
    }
    #pragma unroll
    for (int j = 0; j < 8; j++) acc[j] += acc2[j];

    uint4 ho;
    __half2 q0 = __floats2half2_rn(acc[0], acc[1]);
    __half2 q1 = __floats2half2_rn(acc[2], acc[3]);
    __half2 q2 = __floats2half2_rn(acc[4], acc[5]);
    __half2 q3 = __floats2half2_rn(acc[6], acc[7]);
    ho.x = *reinterpret_cast<uint32_t*>(&q0);
    ho.y = *reinterpret_cast<uint32_t*>(&q1);
    ho.z = *reinterpret_cast<uint32_t*>(&q2);
    ho.w = *reinterpret_cast<uint32_t*>(&q3);
    ((uint4*)g_hf16)[(size_t)i * 32 + t] = ho;
}

// --------------------- fused pooling + readout MLP --------------------------
__global__ void __launch_bounds__(HD) k_pool_readout(
    const float* __restrict__ r1w, const float* __restrict__ r1b,
    const float* __restrict__ r2w, const float* __restrict__ r2b,
    float* __restrict__ out)
{
    int g = blockIdx.x;
    int t = threadIdx.x;
    int beg = g_gstart[g], end = g_gstart[g + 1];
    float s = 0.f, m = -3.402823e38f;
    const __half* hp = g_hf16 + t;
    for (int i = beg; i < end; ++i) {
        float v = __half2float(hp[(size_t)i * HD]);
        s += v;
        m = fmaxf(m, v);
    }
    int cnt = end - beg;
    __shared__ float sh[3 * HD];
    sh[t]          = s;
    sh[HD + t]     = (cnt > 0) ? m : 0.f;
    sh[2 * HD + t] = s / (float)(cnt > 0 ? cnt : 1);
    __syncthreads();

    __shared__ float z[128];
    if (t < 128) {
        float acc = r1b[t];
        for (int k = 0; k < 3 * HD; k++)
            acc = fmaf(sh[k], r1w[k * 128 + t], acc);
        z[t] = (acc > 0.f) ? acc : 0.01f * acc;
    }
    __syncthreads();
    if (t < NO) {
        float o = r2b[t];
        #pragma unroll 4
        for (int k = 0; k < 128; k++)
            o = fmaf(z[k], r2w[k * NO + t], o);
        out[g * NO + t] = o;
    }
}

// -------------------------------- launcher ---------------------------------
extern "C" void kernel_launch(void* const* d_in, const int* in_sizes, int n_in,
                              void* d_out, int out_size)
{
    const float* x      = (const float*)d_in[0];
    const int*   ei     = (const int*)d_in[1];
    const int*   batch  = (const int*)d_in[2];
    const float* enc_w  = (const float*)d_in[3];
    const float* enc_b  = (const float*)d_in[4];
    const float* conv_w = (const float*)d_in[5];
    const float* conv_b = (const float*)d_in[6];
    const float* r1_w   = (const float*)d_in[7];
    const float* r1_b   = (const float*)d_in[8];
    const float* r2_w   = (const float*)d_in[9];
    const float* r2_b   = (const float*)d_in[10];
    float* out = (float*)d_out;

    __half *hf16, *xh, *hw0, *hw1;
    uint32_t *wp_enc, *wp_conv;
    cudaGetSymbolAddress((void**)&hf16, g_hf16);
    cudaGetSymbolAddress((void**)&xh,   g_xh);
    cudaGetSymbolAddress((void**)&hw0,  g_hw0);
    cudaGetSymbolAddress((void**)&hw1,  g_hw1);
    cudaGetSymbolAddress((void**)&wp_enc,  g_wp_enc);
    cudaGetSymbolAddress((void**)&wp_conv, g_wp_conv);

    static cudaStream_t s_side = nullptr;
    static cudaEvent_t  ev_fork = nullptr, ev_csr = nullptr;
    if (!s_side) {
        cudaStreamCreateWithFlags(&s_side, cudaStreamNonBlocking);
        cudaEventCreateWithFlags(&ev_fork, cudaEventDisableTiming);
        cudaEventCreateWithFlags(&ev_csr,  cudaEventDisableTiming);
        cudaFuncSetAttribute(k_agg_gemm,
                             cudaFuncAttributeMaxDynamicSharedMemorySize,
                             FUSED_SMEM);
    }

    const int TB = 256;
    int gN = (NN + TB - 1) / TB;
    int gE = (NE + TB - 1) / TB;
    const int NT = (NN + 127) / 128;     // 391

    // init, then fork CSR chain to side stream
    k_init<<<gN, TB>>>();
    cudaEventRecord(ev_fork, 0);
    cudaStreamWaitEvent(s_side, ev_fork, 0);

    // side: CSR build chain
    k_count_deg<<<gE, TB, 0, s_side>>>(ei);
    k_scan_local<<<SCB, 1024, 0, s_side>>>();
    k_scan_add<<<SCB, 1024, 0, s_side>>>();
    k_fill<<<(ETOT + TB - 1) / TB, TB, 0, s_side>>>(ei);
    cudaEventRecord(ev_csr, s_side);

    // main: convert+pack+gsearch, encoder GEMM, conv GEMM 1 (overlapped)
    {
        int total = NN * FIN / 2 + (FIN / 2) * HD + NL * (HD / 2) * HD + NG + 1;
        k_prep<<<(total + TB - 1) / TB, TB>>>(x, enc_w, conv_w, batch);
    }
    k_gemm_f16<<<dim3(NT, 2), 256>>>(xh, wp_enc, enc_b, hf16, NN, FIN);
    k_gemm_f16<<<dim3(NT, 2), 256>>>(hf16, wp_conv, nullptr, hw0, NN, HD);

    // join: CSR must be ready before fused layers
    cudaStreamWaitEvent(0, ev_csr, 0);

    // fused middle layers: [A1+G2], [A2+G3]
    k_agg_gemm<<<NT, 256, FUSED_SMEM>>>(conv_b, hw0,
                                        wp_conv + (size_t)1 * (HD / 2) * HD, hw1);
    k_agg_gemm<<<NT, 256, FUSED_SMEM>>>(conv_b + HD, hw1,
                                        wp_conv + (size_t)2 * (HD / 2) * HD, hw0);

    // last aggregate + fused pooling/readout
    k_aggregate<<<(NN + 7) / 8, 256>>>(conv_b + 2 * HD, hw0);
    k_pool_readout<<<NG, HD>>>(r1_w, r1_b, r2_w, r2_b, out);
}

// round 16
// speedup vs baseline: 1.2973x; 1.2973x over previous
#include <cuda_runtime.h>
#include <cuda_fp16.h>
#include <cstdint>

// ---------------------------------------------------------------------------
// GCN forward:  N=50000, E=800000, F_IN=128, H=256, G=256, O=32, L=3
// edge_index / batch are int32.
//
// R11-optimum structure: fp16 end-to-end; mma.sync m16n8k16 GEMM (16-k static
// smem tiles); separate high-occupancy aggregate kernels; CSR built on a side
// stream; pool+readout fused; gsearch folded into prep; 2-kernel scan.
// ---------------------------------------------------------------------------

#define NN 50000
#define NE 800000
#define FIN 128
#define HD 256
#define NG 256
#define NO 32
#define NL 3
#define ETOT (NE + NN)
#define SCB 49

// ----------------------------- device scratch ------------------------------
__device__ __half   g_hf16[(size_t)NN * HD];         // fp16 h (GEMM A input)
__device__ __half   g_xh[(size_t)NN * FIN];          // fp16 x
__device__ __half   g_hwh[(size_t)NN * HD];          // fp16 hw (conv GEMM out)
__device__ int      g_counts[NN];
__device__ int      g_cursor[NN];
__device__ float    g_dis[NN];
__device__ int      g_offsets[NN + 1];
__device__ int      g_part[SCB];
__device__ int2     g_csr[ETOT];
__device__ int      g_gstart[NG + 1];
__device__ uint32_t g_wp_enc[(FIN / 2) * HD];        // half2(W[2p][n],W[2p+1][n])
__device__ uint32_t g_wp_conv[NL * (HD / 2) * HD];

// ------------------------------ setup kernels ------------------------------
__global__ void k_init() {
    int i = blockIdx.x * blockDim.x + threadIdx.x;
    if (i < NN) g_counts[i] = 1;                     // self loop
}

__global__ void k_count_deg(const int* __restrict__ ei) {
    int e = blockIdx.x * blockDim.x + threadIdx.x;
    if (e < NE) atomicAdd(&g_counts[ei[NE + e]], 1);
}

__global__ void __launch_bounds__(1024) k_scan_local() {
    __shared__ int sd[1024];
    int t = threadIdx.x;
    int i = blockIdx.x * 1024 + t;
    int v = 0;
    if (i < NN) {
        v = g_counts[i];
        g_dis[i] = rsqrtf((float)v);
    }
    sd[t] = v;
    __syncthreads();
    #pragma unroll
    for (int off = 1; off < 1024; off <<= 1) {
        int tmp = (t >= off) ? sd[t - off] : 0;
        __syncthreads();
        if (t >= off) sd[t] += tmp;
        __syncthreads();
    }
    if (i < NN) g_offsets[i + 1] = sd[t];
    if (t == 1023) g_part[blockIdx.x] = sd[t];
}

// per-block redundant scan of partials; finalize offsets; zero cursor
__global__ void __launch_bounds__(1024) k_scan_add() {
    __shared__ int sp[64];
    int t = threadIdx.x;
    if (t < 64) sp[t] = (t < SCB) ? g_part[t] : 0;
    __syncthreads();
    #pragma unroll
    for (int off = 1; off < 64; off <<= 1) {
        int v = (t < 64 && t >= off) ? sp[t - off] : 0;
        __syncthreads();
        if (t < 64) sp[t] += v;
        __syncthreads();
    }
    int prefix = (blockIdx.x == 0) ? 0 : sp[blockIdx.x - 1];
    int i = blockIdx.x * 1024 + t;
    if (i < NN) {
        g_offsets[i + 1] += prefix;
        g_cursor[i] = 0;
    }
    if (i == 0) g_offsets[0] = 0;
}

// merged self-loop + edge CSR fill
__global__ void k_fill(const int* __restrict__ ei) {
    int idx = blockIdx.x * blockDim.x + threadIdx.x;
    if (idx < NN) {
        int pos = g_offsets[idx] + atomicAdd(&g_cursor[idx], 1);
        float d = g_dis[idx];
        g_csr[pos] = make_int2(idx, __float_as_int(d * d));
    } else if (idx < NN + NE) {
        int e = idx - NN;
        int s = ei[e];
        int d = ei[NE + e];
        int pos = g_offsets[d] + atomicAdd(&g_cursor[d], 1);
        g_csr[pos] = make_int2(s, __float_as_int(g_dis[s] * g_dis[d]));
    }
}

// --------- input convert + weight pack + graph bounds (merged, once) --------
__global__ void __launch_bounds__(256) k_prep(const float* __restrict__ x,
                                              const float* __restrict__ enc_w,
                                              const float* __restrict__ conv_w,
                                              const int* __restrict__ batch) {
    int i = blockIdx.x * blockDim.x + threadIdx.x;
    const int XT  = NN * FIN / 2;
    const int NE_ = (FIN / 2) * HD;
    const int NC_ = NL * (HD / 2) * HD;
    if (i < XT) {
        float2 f = ((const float2*)x)[i];
        ((__half2*)g_xh)[i] = __floats2half2_rn(f.x, f.y);
        return;
    }
    int j = i - XT;
    if (j < NE_) {
        int p = j / HD, n = j % HD;
        __half2 h = __floats2half2_rn(enc_w[(2 * p) * HD + n],
                                      enc_w[(2 * p + 1) * HD + n]);
        g_wp_enc[j] = *reinterpret_cast<uint32_t*>(&h);
        return;
    }
    int r0 = j - NE_;
    if (r0 < NC_) {
        int l = r0 / ((HD / 2) * HD);
        int r = r0 % ((HD / 2) * HD);
        int p = r / HD, n = r % HD;
        const float* W = conv_w + (size_t)l * HD * HD;
        __half2 h = __floats2half2_rn(W[(2 * p) * HD + n],
                                      W[(2 * p + 1) * HD + n]);
        g_wp_conv[r0] = *reinterpret_cast<uint32_t*>(&h);
        return;
    }
    int g = r0 - NC_;
    if (g <= NG) {                       // gstart[g] = lower_bound(batch, g)
        int lo = 0, hi = NN;
        while (lo < hi) {
            int mid = (lo + hi) >> 1;
            if (batch[mid] < g) lo = mid + 1; else hi = mid;
        }
        g_gstart[g] = lo;
    }
}

// ----------------------- fp16 tensor-core GEMM (R11) -------------------------
// Ch[M,256] = A[M,K] @ W[K,256] (+bias). Tile 128x128x16, 256 thr, 8 warps 4x2.
__device__ __forceinline__ void mma_f16(float* c, const uint32_t* a,
                                        uint32_t b0, uint32_t b1) {
    asm volatile(
        "mma.sync.aligned.m16n8k16.row.col.f32.f16.f16.f32 "
        "{%0,%1,%2,%3}, {%4,%5,%6,%7}, {%8,%9}, {%0,%1,%2,%3};"
        : "+f"(c[0]), "+f"(c[1]), "+f"(c[2]), "+f"(c[3])
        : "r"(a[0]), "r"(a[1]), "r"(a[2]), "r"(a[3]), "r"(b0), "r"(b1));
}

__global__ void __launch_bounds__(256) k_gemm_f16(
    const __half* __restrict__ A, const uint32_t* __restrict__ Wp,
    const float* __restrict__ bias, __half* __restrict__ Ch,
    int M, int K)
{
    __shared__ uint32_t As[2][8][136];
    __shared__ uint32_t Bs[2][8][136];

    int tid = threadIdx.x;
    int bm = blockIdx.x * 128;
    int bn = blockIdx.y * 128;

    int lane = tid & 31;
    int warp = tid >> 5;
    int tig  = lane & 3;
    int grp  = lane >> 2;
    int wm   = (warp & 3) * 32;
    int wn   = (warp >> 2) * 64;

    int ar  = bm + (tid >> 1);  if (ar >= M) ar = M - 1;
    int akq = (tid & 1) * 8;
    int ap2 = akq >> 1;
    int bk  = tid >> 5;
    int bc  = (tid & 31) * 4;

    const __half*   Apt = A + (size_t)ar * K + akq;
    const uint32_t* Bpt = Wp + (size_t)bk * HD + bn + bc;

    float acc[2][8][4];
    #pragma unroll
    for (int mt = 0; mt < 2; mt++)
        #pragma unroll
        for (int nt = 0; nt < 8; nt++)
            #pragma unroll
            for (int r = 0; r < 4; r++) acc[mt][nt][r] = 0.f;

    int KT = K >> 4;

    uint4 rA = *(const uint4*)(Apt);
    uint4 rB = *(const uint4*)(Bpt);

    {
        int arow = tid >> 1;
        As[0][ap2 + 0][arow] = rA.x;
        As[0][ap2 + 1][arow] = rA.y;
        As[0][ap2 + 2][arow] = rA.z;
        As[0][ap2 + 3][arow] = rA.w;
        Bs[0][bk][bc + 0] = rB.x;
        Bs[0][bk][bc + 1] = rB.y;
        Bs[0][bk][bc + 2] = rB.z;
        Bs[0][bk][bc + 3] = rB.w;
    }
    __syncthreads();

    for (int kt = 0; kt < KT; kt++) {
        int cur = kt & 1;
        int nxt = cur ^ 1;
        if (kt + 1 < KT) {
            rA = *(const uint4*)(Apt + (kt + 1) * 16);
            rB = *(const uint4*)(Bpt + (size_t)(kt + 1) * 8 * HD);
        }

        uint32_t a[2][4];
        #pragma unroll
        for (int mt = 0; mt < 2; mt++) {
            int rb = wm + mt * 16 + grp;
            a[mt][0] = As[cur][tig][rb];
            a[mt][1] = As[cur][tig][rb + 8];
            a[mt][2] = As[cur][tig + 4][rb];
            a[mt][3] = As[cur][tig + 4][rb + 8];
        }
        #pragma unroll
        for (int nt = 0; nt < 8; nt++) {
            int nb = wn + nt * 8 + grp;
            uint32_t b0 = Bs[cur][tig][nb];
            uint32_t b1 = Bs[cur][tig + 4][nb];
            mma_f16(acc[0][nt], a[0], b0, b1);
            mma_f16(acc[1][nt], a[1], b0, b1);
        }

        if (kt + 1 < KT) {
            int arow = tid >> 1;
            As[nxt][ap2 + 0][arow] = rA.x;
            As[nxt][ap2 + 1][arow] = rA.y;
            As[nxt][ap2 + 2][arow] = rA.z;
            As[nxt][ap2 + 3][arow] = rA.w;
            Bs[nxt][bk][bc + 0] = rB.x;
            Bs[nxt][bk][bc + 1] = rB.y;
            Bs[nxt][bk][bc + 2] = rB.z;
            Bs[nxt][bk][bc + 3] = rB.w;
        }
        __syncthreads();
    }

    #pragma unroll
    for (int mt = 0; mt < 2; mt++) {
        #pragma unroll
        for (int nt = 0; nt < 8; nt++) {
            int col = bn + wn + nt * 8 + tig * 2;
            float b0 = bias ? bias[col]     : 0.f;
            float b1 = bias ? bias[col + 1] : 0.f;
            int r0 = bm + wm + mt * 16 + grp;
            int r1 = r0 + 8;
            if (r0 < M) {
                __half2 v = __floats2half2_rn(acc[mt][nt][0] + b0,
                                              acc[mt][nt][1] + b1);
                *(__half2*)(Ch + (size_t)r0 * HD + col) = v;
            }
            if (r1 < M) {
                __half2 v = __floats2half2_rn(acc[mt][nt][2] + b0,
                                              acc[mt][nt][3] + b1);
                *(__half2*)(Ch + (size_t)r1 * HD + col) = v;
            }
        }
    }
}

// ----------------------------- CSR aggregation -----------------------------
// 8 nodes/block; 32 threads/node; uint4 = 8 fp16 features/thread; fp32 acc.
__global__ void __launch_bounds__(256) k_aggregate(const float* __restrict__ bias) {
    int grpIdx = threadIdx.x >> 5;
    int t      = threadIdx.x & 31;
    int i = blockIdx.x * 8 + grpIdx;
    if (i >= NN) return;
    int beg = g_offsets[i];
    int end = g_offsets[i + 1];

    float acc[8], acc2[8];
    {
        float4 bA = ((const float4*)bias)[t * 2];
        float4 bB = ((const float4*)bias)[t * 2 + 1];
        acc[0] = bA.x; acc[1] = bA.y; acc[2] = bA.z; acc[3] = bA.w;
        acc[4] = bB.x; acc[5] = bB.y; acc[6] = bB.z; acc[7] = bB.w;
        #pragma unroll
        for (int j = 0; j < 8; j++) acc2[j] = 0.f;
    }

    const uint4* hwv = (const uint4*)g_hwh;
    int e = beg;
    for (; e + 2 <= end; e += 2) {
        int2 p0 = __ldg(&g_csr[e]);
        int2 p1 = __ldg(&g_csr[e + 1]);
        float w0 = __int_as_float(p0.y);
        float w1 = __int_as_float(p1.y);
        uint4 v0 = __ldg(&hwv[(size_t)p0.x * 32 + t]);
        uint4 v1 = __ldg(&hwv[(size_t)p1.x * 32 + t]);
        const __half2* h0 = (const __half2*)&v0;
        const __half2* h1 = (const __half2*)&v1;
        #pragma unroll
        for (int j = 0; j < 4; j++) {
            float2 f0 = __half22float2(h0[j]);
            float2 f1 = __half22float2(h1[j]);
            acc[2*j]   = fmaf(w0, f0.x, acc[2*j]);
            acc[2*j+1] = fmaf(w0, f0.y, acc[2*j+1]);
            acc2[2*j]   = fmaf(w1, f1.x, acc2[2*j]);
            acc2[2*j+1] = fmaf(w1, f1.y, acc2[2*j+1]);
        }
    }
    if (e < end) {
        int2 p = __ldg(&g_csr[e]);
        float w = __int_as_float(p.y);
        uint4 v = __ldg(&hwv[(size_t)p.x * 32 + t]);
        const __half2* hh = (const __half2*)&v;
        #pragma unroll
        for (int j = 0; j < 4; j++) {
            float2 f = __half22float2(hh[j]);
            acc[2*j]   = fmaf(w, f.x, acc[2*j]);
            acc[2*j+1] = fmaf(w, f.y, acc[2*j+1]);
        }
    }
    #pragma unroll
    for (int j = 0; j < 8; j++) acc[j] += acc2[j];

    uint4 ho;
    __half2 q0 = __floats2half2_rn(acc[0], acc[1]);
    __half2 q1 = __floats2half2_rn(acc[2], acc[3]);
    __half2 q2 = __floats2half2_rn(acc[4], acc[5]);
    __half2 q3 = __floats2half2_rn(acc[6], acc[7]);
    ho.x = *reinterpret_cast<uint32_t*>(&q0);
    ho.y = *reinterpret_cast<uint32_t*>(&q1);
    ho.z = *reinterpret_cast<uint32_t*>(&q2);
    ho.w = *reinterpret_cast<uint32_t*>(&q3);
    ((uint4*)g_hf16)[(size_t)i * 32 + t] = ho;
}

// --------------------- fused pooling + readout MLP --------------------------
__global__ void __launch_bounds__(HD) k_pool_readout(
    const float* __restrict__ r1w, const float* __restrict__ r1b,
    const float* __restrict__ r2w, const float* __restrict__ r2b,
    float* __restrict__ out)
{
    int g = blockIdx.x;
    int t = threadIdx.x;
    int beg = g_gstart[g], end = g_gstart[g + 1];
    float s = 0.f, m = -3.402823e38f;
    const __half* hp = g_hf16 + t;
    for (int i = beg; i < end; ++i) {
        float v = __half2float(hp[(size_t)i * HD]);
        s += v;
        m = fmaxf(m, v);
    }
    int cnt = end - beg;
    __shared__ float sh[3 * HD];
    sh[t]          = s;
    sh[HD + t]     = (cnt > 0) ? m : 0.f;
    sh[2 * HD + t] = s / (float)(cnt > 0 ? cnt : 1);
    __syncthreads();

    __shared__ float z[128];
    if (t < 128) {
        float acc = r1b[t];
        for (int k = 0; k < 3 * HD; k++)
            acc = fmaf(sh[k], r1w[k * 128 + t], acc);
        z[t] = (acc > 0.f) ? acc : 0.01f * acc;   // leaky_relu(0.01)
    }
    __syncthreads();
    if (t < NO) {
        float o = r2b[t];
        #pragma unroll 4
        for (int k = 0; k < 128; k++)
            o = fmaf(z[k], r2w[k * NO + t], o);
        out[g * NO + t] = o;
    }
}

// -------------------------------- launcher ---------------------------------
extern "C" void kernel_launch(void* const* d_in, const int* in_sizes, int n_in,
                              void* d_out, int out_size)
{
    const float* x      = (const float*)d_in[0];
    const int*   ei     = (const int*)d_in[1];
    const int*   batch  = (const int*)d_in[2];
    const float* enc_w  = (const float*)d_in[3];
    const float* enc_b  = (const float*)d_in[4];
    const float* conv_w = (const float*)d_in[5];
    const float* conv_b = (const float*)d_in[6];
    const float* r1_w   = (const float*)d_in[7];
    const float* r1_b   = (const float*)d_in[8];
    const float* r2_w   = (const float*)d_in[9];
    const float* r2_b   = (const float*)d_in[10];
    float* out = (float*)d_out;

    __half *hf16, *xh, *hwh;
    uint32_t *wp_enc, *wp_conv;
    cudaGetSymbolAddress((void**)&hf16, g_hf16);
    cudaGetSymbolAddress((void**)&xh,   g_xh);
    cudaGetSymbolAddress((void**)&hwh,  g_hwh);
    cudaGetSymbolAddress((void**)&wp_enc,  g_wp_enc);
    cudaGetSymbolAddress((void**)&wp_conv, g_wp_conv);

    static cudaStream_t s_side = nullptr;
    static cudaEvent_t  ev_fork = nullptr, ev_join = nullptr;
    if (!s_side) {
        cudaStreamCreateWithFlags(&s_side, cudaStreamNonBlocking);
        cudaEventCreateWithFlags(&ev_fork, cudaEventDisableTiming);
        cudaEventCreateWithFlags(&ev_join, cudaEventDisableTiming);
    }

    const int TB = 256;
    int gN = (NN + TB - 1) / TB;
    int gE = (NE + TB - 1) / TB;
    dim3 grid((NN + 127) / 128, HD / 128);

    // init on origin stream, then fork CSR chain to side stream
    k_init<<<gN, TB>>>();
    cudaEventRecord(ev_fork, 0);
    cudaStreamWaitEvent(s_side, ev_fork, 0);

    // side: CSR build chain
    k_count_deg<<<gE, TB, 0, s_side>>>(ei);
    k_scan_local<<<SCB, 1024, 0, s_side>>>();
    k_scan_add<<<SCB, 1024, 0, s_side>>>();
    k_fill<<<(ETOT + TB - 1) / TB, TB, 0, s_side>>>(ei);
    cudaEventRecord(ev_join, s_side);

    // origin: convert+pack+gsearch, encoder GEMM (overlapped with side)
    {
        int total = NN * FIN / 2 + (FIN / 2) * HD + NL * (HD / 2) * HD + NG + 1;
        k_prep<<<(total + TB - 1) / TB, TB>>>(x, enc_w, conv_w, batch);
    }
    k_gemm_f16<<<grid, 256>>>(xh, wp_enc, enc_b, hf16, NN, FIN);

    // join: CSR must be ready before the aggregates
    cudaStreamWaitEvent(0, ev_join, 0);

    // conv layers
    for (int l = 0; l < NL; l++) {
        k_gemm_f16<<<grid, 256>>>(hf16, wp_conv + (size_t)l * (HD / 2) * HD,
                                  nullptr, hwh, NN, HD);
        k_aggregate<<<(NN + 7) / 8, 256>>>(conv_b + (size_t)l * HD);
    }

    // fused pooling + readout
    k_pool_readout<<<NG, HD>>>(r1_w, r1_b, r2_w, r2_b, out);
}

// round 17
// speedup vs baseline: 1.3276x; 1.0234x over previous
#include <cuda_runtime.h>
#include <cuda_fp16.h>
#include <cstdint>

// ---------------------------------------------------------------------------
// GCN forward:  N=50000, E=800000, F_IN=128, H=256, G=256, O=32, L=3
// edge_index / batch are int32.
//
// R11-optimum structure + encoder/conv1 GEMM fusion:
//   hw1 = (x@We + be)@W1 = x@(We@W1) + be@W1   -> one K=128 GEMM instead of
//   an encoder GEMM plus a K=256 conv GEMM.  W'=We@W1 precomputed per launch.
// ---------------------------------------------------------------------------

#define NN 50000
#define NE 800000
#define FIN 128
#define HD 256
#define NG 256
#define NO 32
#define NL 3
#define ETOT (NE + NN)
#define SCB 49

// ----------------------------- device scratch ------------------------------
__device__ __half   g_hf16[(size_t)NN * HD];         // fp16 h (GEMM A input)
__device__ __half   g_xh[(size_t)NN * FIN];          // fp16 x
__device__ __half   g_hwh[(size_t)NN * HD];          // fp16 hw (conv GEMM out)
__device__ int      g_counts[NN];
__device__ int      g_cursor[NN];
__device__ float    g_dis[NN];
__device__ int      g_offsets[NN + 1];
__device__ int      g_part[SCB];
__device__ int2     g_csr[ETOT];
__device__ int      g_gstart[NG + 1];
__device__ uint32_t g_wp_fused[(FIN / 2) * HD];      // half2 pack of We@W1
__device__ float    g_bf[HD];                        // be@W1
__device__ uint32_t g_wp_conv[NL * (HD / 2) * HD];   // half2 pack of conv_w^T-pairs

// ------------------------------ setup kernels ------------------------------
__global__ void k_init() {
    int i = blockIdx.x * blockDim.x + threadIdx.x;
    if (i < NN) g_counts[i] = 1;                     // self loop
}

__global__ void k_count_deg(const int* __restrict__ ei) {
    int e = blockIdx.x * blockDim.x + threadIdx.x;
    if (e < NE) atomicAdd(&g_counts[ei[NE + e]], 1);
}

__global__ void __launch_bounds__(1024) k_scan_local() {
    __shared__ int sd[1024];
    int t = threadIdx.x;
    int i = blockIdx.x * 1024 + t;
    int v = 0;
    if (i < NN) {
        v = g_counts[i];
        g_dis[i] = rsqrtf((float)v);
    }
    sd[t] = v;
    __syncthreads();
    #pragma unroll
    for (int off = 1; off < 1024; off <<= 1) {
        int tmp = (t >= off) ? sd[t - off] : 0;
        __syncthreads();
        if (t >= off) sd[t] += tmp;
        __syncthreads();
    }
    if (i < NN) g_offsets[i + 1] = sd[t];
    if (t == 1023) g_part[blockIdx.x] = sd[t];
}

// per-block redundant scan of partials; finalize offsets; zero cursor
__global__ void __launch_bounds__(1024) k_scan_add() {
    __shared__ int sp[64];
    int t = threadIdx.x;
    if (t < 64) sp[t] = (t < SCB) ? g_part[t] : 0;
    __syncthreads();
    #pragma unroll
    for (int off = 1; off < 64; off <<= 1) {
        int v = (t < 64 && t >= off) ? sp[t - off] : 0;
        __syncthreads();
        if (t < 64) sp[t] += v;
        __syncthreads();
    }
    int prefix = (blockIdx.x == 0) ? 0 : sp[blockIdx.x - 1];
    int i = blockIdx.x * 1024 + t;
    if (i < NN) {
        g_offsets[i + 1] += prefix;
        g_cursor[i] = 0;
    }
    if (i == 0) g_offsets[0] = 0;
}

// merged self-loop + edge CSR fill
__global__ void k_fill(const int* __restrict__ ei) {
    int idx = blockIdx.x * blockDim.x + threadIdx.x;
    if (idx < NN) {
        int pos = g_offsets[idx] + atomicAdd(&g_cursor[idx], 1);
        float d = g_dis[idx];
        g_csr[pos] = make_int2(idx, __float_as_int(d * d));
    } else if (idx < NN + NE) {
        int e = idx - NN;
        int s = ei[e];
        int d = ei[NE + e];
        int pos = g_offsets[d] + atomicAdd(&g_cursor[d], 1);
        g_csr[pos] = make_int2(s, __float_as_int(g_dis[s] * g_dis[d]));
    }
}

// --------- fused-weight precompute: W' = We@W1 (packed), b' = be@W1 ---------
// 16384 threads: thread (p, j) computes W'[2p][j], W'[2p+1][j] in fp32,
// packs to half2. Threads with idx < HD also compute b'[j].
__global__ void __launch_bounds__(256) k_wfuse(const float* __restrict__ enc_w,
                                               const float* __restrict__ conv_w,
                                               const float* __restrict__ enc_b) {
    int idx = blockIdx.x * blockDim.x + threadIdx.x;
    const int TOT = (FIN / 2) * HD;
    if (idx < TOT) {
        int p = idx / HD, j = idx % HD;
        const float* a0 = enc_w + (size_t)(2 * p) * HD;       // row 2p of We [128][256]
        const float* a1 = enc_w + (size_t)(2 * p + 1) * HD;
        float s0 = 0.f, s1 = 0.f;
        #pragma unroll 4
        for (int k = 0; k < HD; k++) {
            float b = __ldg(&conv_w[(size_t)k * HD + j]);     // W1[k][j]
            s0 = fmaf(__ldg(&a0[k]), b, s0);
            s1 = fmaf(__ldg(&a1[k]), b, s1);
        }
        __half2 h = __floats2half2_rn(s0, s1);
        g_wp_fused[idx] = *reinterpret_cast<uint32_t*>(&h);
    }
    if (idx < HD) {
        float s = 0.f;
        #pragma unroll 4
        for (int k = 0; k < HD; k++)
            s = fmaf(__ldg(&enc_b[k]), __ldg(&conv_w[(size_t)k * HD + idx]), s);
        g_bf[idx] = s;
    }
}

// NOTE: fused weight W'[i][j] = sum_k We[i][k]*W1[k][j]; We is [FIN][HD]
// (fan_in x H) so row i of We has HD=256 entries: the k-loop above runs over
// HD. W' is [FIN][HD]; packing pairs rows (2p,2p+1) along the K=FIN dim.

// --------- input convert + weight pack + graph bounds (merged, once) --------
__global__ void __launch_bounds__(256) k_prep(const float* __restrict__ x,
                                              const float* __restrict__ conv_w,
                                              const int* __restrict__ batch) {
    int i = blockIdx.x * blockDim.x + threadIdx.x;
    const int XT  = NN * FIN / 2;
    const int NC_ = NL * (HD / 2) * HD;
    if (i < XT) {
        float2 f = ((const float2*)x)[i];
        ((__half2*)g_xh)[i] = __floats2half2_rn(f.x, f.y);
        return;
    }
    int r0 = i - XT;
    if (r0 < NC_) {
        int l = r0 / ((HD / 2) * HD);
        int r = r0 % ((HD / 2) * HD);
        int p = r / HD, n = r % HD;
        const float* W = conv_w + (size_t)l * HD * HD;
        __half2 h = __floats2half2_rn(W[(2 * p) * HD + n],
                                      W[(2 * p + 1) * HD + n]);
        g_wp_conv[r0] = *reinterpret_cast<uint32_t*>(&h);
        return;
    }
    int g = r0 - NC_;
    if (g <= NG) {                       // gstart[g] = lower_bound(batch, g)
        int lo = 0, hi = NN;
        while (lo < hi) {
            int mid = (lo + hi) >> 1;
            if (batch[mid] < g) lo = mid + 1; else hi = mid;
        }
        g_gstart[g] = lo;
    }
}

// ----------------------- fp16 tensor-core GEMM (R11) -------------------------
// Ch[M,256] = A[M,K] @ W[K,256] (+bias). Tile 128x128x16, 256 thr, 8 warps 4x2.
__device__ __forceinline__ void mma_f16(float* c, const uint32_t* a,
                                        uint32_t b0, uint32_t b1) {
    asm volatile(
        "mma.sync.aligned.m16n8k16.row.col.f32.f16.f16.f32 "
        "{%0,%1,%2,%3}, {%4,%5,%6,%7}, {%8,%9}, {%0,%1,%2,%3};"
        : "+f"(c[0]), "+f"(c[1]), "+f"(c[2]), "+f"(c[3])
        : "r"(a[0]), "r"(a[1]), "r"(a[2]), "r"(a[3]), "r"(b0), "r"(b1));
}

__global__ void __launch_bounds__(256) k_gemm_f16(
    const __half* __restrict__ A, const uint32_t* __restrict__ Wp,
    const float* __restrict__ bias, __half* __restrict__ Ch,
    int M, int K)
{
    __shared__ uint32_t As[2][8][136];
    __shared__ uint32_t Bs[2][8][136];

    int tid = threadIdx.x;
    int bm = blockIdx.x * 128;
    int bn = blockIdx.y * 128;

    int lane = tid & 31;
    int warp = tid >> 5;
    int tig  = lane & 3;
    int grp  = lane >> 2;
    int wm   = (warp & 3) * 32;
    int wn   = (warp >> 2) * 64;

    int ar  = bm + (tid >> 1);  if (ar >= M) ar = M - 1;
    int akq = (tid & 1) * 8;
    int ap2 = akq >> 1;
    int bk  = tid >> 5;
    int bc  = (tid & 31) * 4;

    const __half*   Apt = A + (size_t)ar * K + akq;
    const uint32_t* Bpt = Wp + (size_t)bk * HD + bn + bc;

    float acc[2][8][4];
    #pragma unroll
    for (int mt = 0; mt < 2; mt++)
        #pragma unroll
        for (int nt = 0; nt < 8; nt++)
            #pragma unroll
            for (int r = 0; r < 4; r++) acc[mt][nt][r] = 0.f;

    int KT = K >> 4;

    uint4 rA = *(const uint4*)(Apt);
    uint4 rB = *(const uint4*)(Bpt);

    {
        int arow = tid >> 1;
        As[0][ap2 + 0][arow] = rA.x;
        As[0][ap2 + 1][arow] = rA.y;
        As[0][ap2 + 2][arow] = rA.z;
        As[0][ap2 + 3][arow] = rA.w;
        Bs[0][bk][bc + 0] = rB.x;
        Bs[0][bk][bc + 1] = rB.y;
        Bs[0][bk][bc + 2] = rB.z;
        Bs[0][bk][bc + 3] = rB.w;
    }
    __syncthreads();

    for (int kt = 0; kt < KT; kt++) {
        int cur = kt & 1;
        int nxt = cur ^ 1;
        if (kt + 1 < KT) {
            rA = *(const uint4*)(Apt + (kt + 1) * 16);
            rB = *(const uint4*)(Bpt + (size_t)(kt + 1) * 8 * HD);
        }

        uint32_t a[2][4];
        #pragma unroll
        for (int mt = 0; mt < 2; mt++) {
            int rb = wm + mt * 16 + grp;
            a[mt][0] = As[cur][tig][rb];
            a[mt][1] = As[cur][tig][rb + 8];
            a[mt][2] = As[cur][tig + 4][rb];
            a[mt][3] = As[cur][tig + 4][rb + 8];
        }
        #pragma unroll
        for (int nt = 0; nt < 8; nt++) {
            int nb = wn + nt * 8 + grp;
            uint32_t b0 = Bs[cur][tig][nb];
            uint32_t b1 = Bs[cur][tig + 4][nb];
            mma_f16(acc[0][nt], a[0], b0, b1);
            mma_f16(acc[1][nt], a[1], b0, b1);
        }

        if (kt + 1 < KT) {
            int arow = tid >> 1;
            As[nxt][ap2 + 0][arow] = rA.x;
            As[nxt][ap2 + 1][arow] = rA.y;
            As[nxt][ap2 + 2][arow] = rA.z;
            As[nxt][ap2 + 3][arow] = rA.w;
            Bs[nxt][bk][bc + 0] = rB.x;
            Bs[nxt][bk][bc + 1] = rB.y;
            Bs[nxt][bk][bc + 2] = rB.z;
            Bs[nxt][bk][bc + 3] = rB.w;
        }
        __syncthreads();
    }

    #pragma unroll
    for (int mt = 0; mt < 2; mt++) {
        #pragma unroll
        for (int nt = 0; nt < 8; nt++) {
            int col = bn + wn + nt * 8 + tig * 2;
            float b0 = bias ? bias[col]     : 0.f;
            float b1 = bias ? bias[col + 1] : 0.f;
            int r0 = bm + wm + mt * 16 + grp;
            int r1 = r0 + 8;
            if (r0 < M) {
                __half2 v = __floats2half2_rn(acc[mt][nt][0] + b0,
                                              acc[mt][nt][1] + b1);
                *(__half2*)(Ch + (size_t)r0 * HD + col) = v;
            }
            if (r1 < M) {
                __half2 v = __floats2half2_rn(acc[mt][nt][2] + b0,
                                              acc[mt][nt][3] + b1);
                *(__half2*)(Ch + (size_t)r1 * HD + col) = v;
            }
        }
    }
}

// ----------------------------- CSR aggregation -----------------------------
// 8 nodes/block; 32 threads/node; uint4 = 8 fp16 features/thread; fp32 acc.
__global__ void __launch_bounds__(256) k_aggregate(const float* __restrict__ bias) {
    int grpIdx = threadIdx.x >> 5;
    int t      = threadIdx.x & 31;
    int i = blockIdx.x * 8 + grpIdx;
    if (i >= NN) return;
    int beg = g_offsets[i];
    int end = g_offsets[i + 1];

    float acc[8], acc2[8];
    {
        float4 bA = ((const float4*)bias)[t * 2];
        float4 bB = ((const float4*)bias)[t * 2 + 1];
        acc[0] = bA.x; acc[1] = bA.y; acc[2] = bA.z; acc[3] = bA.w;
        acc[4] = bB.x; acc[5] = bB.y; acc[6] = bB.z; acc[7] = bB.w;
        #pragma unroll
        for (int j = 0; j < 8; j++) acc2[j] = 0.f;
    }

    const uint4* hwv = (const uint4*)g_hwh;
    int e = beg;
    for (; e + 2 <= end; e += 2) {
        int2 p0 = __ldg(&g_csr[e]);
        int2 p1 = __ldg(&g_csr[e + 1]);
        float w0 = __int_as_float(p0.y);
        float w1 = __int_as_float(p1.y);
        uint4 v0 = __ldg(&hwv[(size_t)p0.x * 32 + t]);
        uint4 v1 = __ldg(&hwv[(size_t)p1.x * 32 + t]);
        const __half2* h0 = (const __half2*)&v0;
        const __half2* h1 = (const __half2*)&v1;
        #pragma unroll
        for (int j = 0; j < 4; j++) {
            float2 f0 = __half22float2(h0[j]);
            float2 f1 = __half22float2(h1[j]);
            acc[2*j]   = fmaf(w0, f0.x, acc[2*j]);
            acc[2*j+1] = fmaf(w0, f0.y, acc[2*j+1]);
            acc2[2*j]   = fmaf(w1, f1.x, acc2[2*j]);
            acc2[2*j+1] = fmaf(w1, f1.y, acc2[2*j+1]);
        }
    }
    if (e < end) {
        int2 p = __ldg(&g_csr[e]);
        float w = __int_as_float(p.y);
        uint4 v = __ldg(&hwv[(size_t)p.x * 32 + t]);
        const __half2* hh = (const __half2*)&v;
        #pragma unroll
        for (int j = 0; j < 4; j++) {
            float2 f = __half22float2(hh[j]);
            acc[2*j]   = fmaf(w, f.x, acc[2*j]);
            acc[2*j+1] = fmaf(w, f.y, acc[2*j+1]);
        }
    }
    #pragma unroll
    for (int j = 0; j < 8; j++) acc[j] += acc2[j];

    uint4 ho;
    __half2 q0 = __floats2half2_rn(acc[0], acc[1]);
    __half2 q1 = __floats2half2_rn(acc[2], acc[3]);
    __half2 q2 = __floats2half2_rn(acc[4], acc[5]);
    __half2 q3 = __floats2half2_rn(acc[6], acc[7]);
    ho.x = *reinterpret_cast<uint32_t*>(&q0);
    ho.y = *reinterpret_cast<uint32_t*>(&q1);
    ho.z = *reinterpret_cast<uint32_t*>(&q2);
    ho.w = *reinterpret_cast<uint32_t*>(&q3);
    ((uint4*)g_hf16)[(size_t)i * 32 + t] = ho;
}

// --------------------- fused pooling + readout MLP --------------------------
__global__ void __launch_bounds__(HD) k_pool_readout(
    const float* __restrict__ r1w, const float* __restrict__ r1b,
    const float* __restrict__ r2w, const float* __restrict__ r2b,
    float* __restrict__ out)
{
    int g = blockIdx.x;
    int t = threadIdx.x;
    int beg = g_gstart[g], end = g_gstart[g + 1];
    float s = 0.f, m = -3.402823e38f;
    const __half* hp = g_hf16 + t;
    for (int i = beg; i < end; ++i) {
        float v = __half2float(hp[(size_t)i * HD]);
        s += v;
        m = fmaxf(m, v);
    }
    int cnt = end - beg;
    __shared__ float sh[3 * HD];
    sh[t]          = s;
    sh[HD + t]     = (cnt > 0) ? m : 0.f;
    sh[2 * HD + t] = s / (float)(cnt > 0 ? cnt : 1);
    __syncthreads();

    __shared__ float z[128];
    if (t < 128) {
        float acc = r1b[t];
        for (int k = 0; k < 3 * HD; k++)
            acc = fmaf(sh[k], r1w[k * 128 + t], acc);
        z[t] = (acc > 0.f) ? acc : 0.01f * acc;   // leaky_relu(0.01)
    }
    __syncthreads();
    if (t < NO) {
        float o = r2b[t];
        #pragma unroll 4
        for (int k = 0; k < 128; k++)
            o = fmaf(z[k], r2w[k * NO + t], o);
        out[g * NO + t] = o;
    }
}

// -------------------------------- launcher ---------------------------------
extern "C" void kernel_launch(void* const* d_in, const int* in_sizes, int n_in,
                              void* d_out, int out_size)
{
    const float* x      = (const float*)d_in[0];
    const int*   ei     = (const int*)d_in[1];
    const int*   batch  = (const int*)d_in[2];
    const float* enc_w  = (const float*)d_in[3];
    const float* enc_b  = (const float*)d_in[4];
    const float* conv_w = (const float*)d_in[5];
    const float* conv_b = (const float*)d_in[6];
    const float* r1_w   = (const float*)d_in[7];
    const float* r1_b   = (const float*)d_in[8];
    const float* r2_w   = (const float*)d_in[9];
    const float* r2_b   = (const float*)d_in[10];
    float* out = (float*)d_out;

    __half *hf16, *xh, *hwh;
    uint32_t *wp_fused, *wp_conv;
    float *bf;
    cudaGetSymbolAddress((void**)&hf16, g_hf16);
    cudaGetSymbolAddress((void**)&xh,   g_xh);
    cudaGetSymbolAddress((void**)&hwh,  g_hwh);
    cudaGetSymbolAddress((void**)&wp_fused, g_wp_fused);
    cudaGetSymbolAddress((void**)&wp_conv,  g_wp_conv);
    cudaGetSymbolAddress((void**)&bf,       g_bf);

    static cudaStream_t s_side = nullptr;
    static cudaEvent_t  ev_fork = nullptr, ev_join = nullptr;
    if (!s_side) {
        cudaStreamCreateWithFlags(&s_side, cudaStreamNonBlocking);
        cudaEventCreateWithFlags(&ev_fork, cudaEventDisableTiming);
        cudaEventCreateWithFlags(&ev_join, cudaEventDisableTiming);
    }

    const int TB = 256;
    int gN = (NN + TB - 1) / TB;
    int gE = (NE + TB - 1) / TB;
    dim3 grid((NN + 127) / 128, HD / 128);

    // init on origin stream, then fork CSR chain to side stream
    k_init<<<gN, TB>>>();
    cudaEventRecord(ev_fork, 0);
    cudaStreamWaitEvent(s_side, ev_fork, 0);

    // side: CSR build chain
    k_count_deg<<<gE, TB, 0, s_side>>>(ei);
    k_scan_local<<<SCB, 1024, 0, s_side>>>();
    k_scan_add<<<SCB, 1024, 0, s_side>>>();
    k_fill<<<(ETOT + TB - 1) / TB, TB, 0, s_side>>>(ei);
    cudaEventRecord(ev_join, s_side);

    // origin: fused-weight precompute, convert+pack+gsearch, fused GEMM
    k_wfuse<<<((FIN / 2) * HD + TB - 1) / TB, TB>>>(enc_w, conv_w, enc_b);
    {
        int total = NN * FIN / 2 + NL * (HD / 2) * HD + NG + 1;
        k_prep<<<(total + TB - 1) / TB, TB>>>(x, conv_w, batch);
    }
    // hw1 = x @ (We@W1) + be@W1   (replaces encoder GEMM + conv GEMM 1)
    k_gemm_f16<<<grid, 256>>>(xh, wp_fused, bf, hwh, NN, FIN);

    // join: CSR must be ready before the aggregates
    cudaStreamWaitEvent(0, ev_join, 0);

    // layer 1 aggregate, then remaining conv layers
    k_aggregate<<<(NN + 7) / 8, 256>>>(conv_b);
    for (int l = 1; l < NL; l++) {
        k_gemm_f16<<<grid, 256>>>(hf16, wp_conv + (size_t)l * (HD / 2) * HD,
                                  nullptr, hwh, NN, HD);
        k_aggregate<<<(NN + 7) / 8, 256>>>(conv_b + (size_t)l * HD);
    }

    // fused pooling + readout
    k_pool_readout<<<NG, HD>>>(r1_w, r1_b, r2_w, r2_b, out);
}